// round 9
// baseline (speedup 1.0000x reference)
#include <cuda_runtime.h>
#include <cuda_bf16.h>

#define HID 32
#define CUTOFF_SQ 6.25f
#define THREADS 256
#define TBL 2048        // intervals over r^2 in [0, CUTOFF_SQ); TBL+1 entries
#define NMAX 4096
#define JCHUNK 32

__device__ float  g_tbl[TBL + 1];   // 0.5 * e(r(sqrt(u)))  (half: each pair counted twice)
__device__ float4 g_pos[NMAX];

// Setup: zero out, pack coords to float4, build half-energy table over r^2.
// One warp per table entry: lane = hidden unit, warp-shuffle reduce.
__global__ __launch_bounds__(THREADS)
void setup_kernel(const float* __restrict__ xyz,
                  const float* __restrict__ W1,
                  const float* __restrict__ b1,
                  const float* __restrict__ W2,
                  const float* __restrict__ b2,
                  float* __restrict__ out,
                  int n) {
    int t = blockIdx.x * blockDim.x + threadIdx.x;
    if (t == 0) out[0] = 0.0f;

    if (t < n) {
        g_pos[t] = make_float4(xyz[3 * t + 0], xyz[3 * t + 1], xyz[3 * t + 2], 0.0f);
    }

    int warp = t >> 5;
    int lane = t & 31;
    if (warp <= TBL) {
        float r2 = (CUTOFF_SQ / (float)TBL) * (float)warp;
        float r  = sqrtf(r2);
        float v  = W2[lane] * tanhf(fmaf(r, W1[lane], b1[lane]));
        #pragma unroll
        for (int off = 16; off > 0; off >>= 1)
            v += __shfl_xor_sync(0xFFFFFFFFu, v, off);
        if (lane == 0) g_tbl[warp] = 0.5f * (v + b2[0]);
    }
}

// Grid: (ceil(n/256), ceil(n/JCHUNK)). Thread owns atom i; block's inner loop
// runs over a fixed JCHUNK j-range — every lane reads the same j (L1 broadcast).
// Branch-free inner loop: misses clamp to the table tail and get FSEL'd to 0.
__global__ __launch_bounds__(THREADS)
void pair_energy_kernel(const float* __restrict__ cell_diag,
                        float* __restrict__ out,
                        int n) {
    __shared__ float warp_sums[THREADS / 32];

    const int tid = threadIdx.x;
    const int i = blockIdx.x * THREADS + tid;

    const float Lx = cell_diag[0], Ly = cell_diag[1], Lz = cell_diag[2];
    const float iLx = 1.0f / Lx, iLy = 1.0f / Ly, iLz = 1.0f / Lz;
    const float invDr2 = (float)TBL / CUTOFF_SQ;
    const float r2clamp = CUTOFF_SQ * (1.0f - 1.0f / (float)TBL);  // keep k <= TBL-1

    float acc = 0.0f;

    if (i < n) {
        const float4 pi = g_pos[i];
        const int j0 = blockIdx.y * JCHUNK;
        const int jend = (j0 + JCHUNK < n) ? (j0 + JCHUNK) : n;

        #pragma unroll 8
        for (int j = j0; j < jend; j++) {
            float4 pj = g_pos[j];
            float dx = pj.x - pi.x;
            float dy = pj.y - pi.y;
            float dz = pj.z - pi.z;

            dx = fmaf(rintf(dx * iLx), -Lx, dx);
            dy = fmaf(rintf(dy * iLy), -Ly, dy);
            dz = fmaf(rintf(dz * iLz), -Lz, dz);

            float r2 = fmaf(dx, dx, fmaf(dy, dy, dz * dz));

            bool hit = (r2 < CUTOFF_SQ) && (r2 > 0.0f);

            float t = fminf(r2, r2clamp) * invDr2;
            int k = (int)t;
            float f = t - (float)k;
            float e0 = g_tbl[k];
            float e1 = g_tbl[k + 1];
            float e = fmaf(f, e1 - e0, e0);

            acc += hit ? e : 0.0f;
        }
    }

    #pragma unroll
    for (int off = 16; off > 0; off >>= 1)
        acc += __shfl_down_sync(0xFFFFFFFFu, acc, off);

    int lane = tid & 31;
    int wid = tid >> 5;
    if (lane == 0) warp_sums[wid] = acc;
    __syncthreads();

    if (wid == 0) {
        float v = (lane < THREADS / 32) ? warp_sums[lane] : 0.0f;
        #pragma unroll
        for (int off = 16; off > 0; off >>= 1)
            v += __shfl_down_sync(0xFFFFFFFFu, v, off);
        if (lane == 0) {
            atomicAdd(out, v);
        }
    }
}

extern "C" void kernel_launch(void* const* d_in, const int* in_sizes, int n_in,
                              void* d_out, int out_size) {
    const float* xyz       = (const float*)d_in[0];
    const float* cell_diag = (const float*)d_in[1];
    const float* W1        = (const float*)d_in[2];
    const float* b1        = (const float*)d_in[3];
    const float* W2        = (const float*)d_in[4];
    const float* b2        = (const float*)d_in[5];
    float* out = (float*)d_out;

    int n = in_sizes[0] / 3;

    long setup_threads_tbl = (long)(TBL + 1) * 32;
    long setup_threads = setup_threads_tbl > n ? setup_threads_tbl : n;
    int setup_blocks = (int)((setup_threads + THREADS - 1) / THREADS);
    setup_kernel<<<setup_blocks, THREADS>>>(xyz, W1, b1, W2, b2, out, n);

    dim3 grid((n + THREADS - 1) / THREADS, (n + JCHUNK - 1) / JCHUNK);
    pair_energy_kernel<<<grid, THREADS>>>(cell_diag, out, n);
}